// round 13
// baseline (speedup 1.0000x reference)
#include <cuda_runtime.h>
#include <cstdint>

#define BB 64
#define CC 4096
#define IND 512
#define OO 16
#define TI 32                 // i-tile: full 128B per (b,c) row
#define NTILES (IND / TI)     // 16
#define WARPS 4
#define NTH (32 * WARPS)
#define CAPS_CTA WARPS        // 1 capsule per warp
#define BH 32                 // b-rows per CTA (page-set split, proven R9)
#define PIPE 3

#define XSTG 1024             // 32 rows x 32 words of x per warp-stage
#define WSTG 512              // 32 i-rows x 16 o of W per warp-stage
#define STG (XSTG + WSTG)     // 1536 floats = 6 KB per warp-stage
#define SMEM_FLOATS (PIPE * WARPS * STG)   // 18432 floats = 72 KB

// ---- packed f32x2 helpers ----
__device__ __forceinline__ uint64_t pack_dup(float x) {
    uint64_t r;
    asm("mov.b64 %0, {%1, %1};" : "=l"(r) : "f"(x));
    return r;
}
__device__ __forceinline__ void fma2(uint64_t& d, uint64_t a, uint64_t b) {
    asm("fma.rn.f32x2 %0, %1, %2, %0;" : "+l"(d) : "l"(a), "l"(b));
}
__device__ __forceinline__ void unpack2(uint64_t v, float& lo, float& hi) {
    asm("mov.b64 {%0, %1}, %2;" : "=f"(lo), "=f"(hi) : "l"(v));
}

// ---- cp.async 16B, L1-bypass ----
__device__ __forceinline__ void cp16(void* dst_smem, const void* src) {
    uint32_t d = (uint32_t)__cvta_generic_to_shared(dst_smem);
    asm volatile("cp.async.cg.shared.global [%0], [%1], 16;"
                 :: "r"(d), "l"(src) : "memory");
}
__device__ __forceinline__ void cp_commit() {
    asm volatile("cp.async.commit_group;" ::: "memory");
}
__device__ __forceinline__ void cp_wait2() {
    asm volatile("cp.async.wait_group 2;" ::: "memory");
}
__device__ __forceinline__ void cp_wait1() {
    asm volatile("cp.async.wait_group 1;" ::: "memory");
}
__device__ __forceinline__ void cp_wait0() {
    asm volatile("cp.async.wait_group 0;" ::: "memory");
}

extern __shared__ float sm[];

__global__ __launch_bounds__(NTH)
void primarycaps_kernel(const float* __restrict__ x,
                        const float* __restrict__ W,
                        const float* __restrict__ bias,
                        float* __restrict__ out)
{
    const int t    = threadIdx.x;
    const int wid  = t >> 5;
    const int lane = t & 31;

    // PAIR-ADJACENT SCHEDULING: blockIdx.x = b-half (fast axis) -> the two
    // CTAs sharing this CTA's W slice are linear neighbors (L2 reuse).
    const int c  = blockIdx.y * CAPS_CTA + wid;   // this warp's capsule
    const int b0 = blockIdx.x * BH;               // this CTA's b-half

    // compute map: 8 b-groups x 4 o-quarters  (mb=4, nb=4 per lane)
    const int tb = lane & 7;          // owns rows tb + 8k (k=0..3)
    const int to = lane >> 3;         // o-quarter: o = to*4 .. to*4+3

    // x staging map: one instr = 4 full 128B lines (4 rows x 8 chunks)
    const int srow = lane >> 3;       // local row 0..3 within group of 4
    const int sch  = lane & 7;        // 16B chunk 0..7 within 128B row

    // per-warp smem stage bases
    float* stg[PIPE];
    #pragma unroll
    for (int s = 0; s < PIPE; ++s)
        stg[s] = sm + (s * WARPS + wid) * STG;

    // ---- accumulators: 4 b-rows x 2 o-pairs (packed f32x2) ----
    uint64_t acc[4][2];
    #pragma unroll
    for (int k = 0; k < 4; ++k) {
        acc[k][0] = 0ULL;
        acc[k][1] = 0ULL;
    }

    // ---- stage helper: tile jt into buffer bf (this warp only) ----
    auto stage = [&](int bf, int jt) {
        float* dx = stg[bf];                   // x at +0, W at +XSTG
        // x: 8 instrs, each = 4 rows x 128B (full lines)
        #pragma unroll
        for (int g = 0; g < 8; ++g) {
            const int row = g * 4 + srow;      // 0..31
            cp16(&dx[row * 32 + ((sch ^ (row & 7)) * 4)],
                 x + ((size_t)(b0 + row) * CC + c) * IND
                   + (size_t)jt * TI + sch * 4);
        }
        // W: 4 instrs of 512B contiguous (full 2KB tile, linear layout)
        float* dw = stg[bf] + XSTG;
        #pragma unroll
        for (int m = 0; m < 4; ++m) {
            const int ofs = m * 128 + lane * 4;
            cp16(&dw[ofs],
                 W + ((size_t)c * IND + (size_t)jt * TI) * OO + ofs);
        }
        cp_commit();
    };

    // ---- prologue: 2 stages in flight ----
    stage(0, 0);
    stage(1, 1);

    int bj = 0;                        // j % PIPE
    for (int j = 0; j < NTILES; ++j) {
        // issue stage j+2 into buffer (j+2)%3 (freed last iteration)
        if (j + 2 < NTILES) {
            int bs = bj + 2; if (bs >= PIPE) bs -= PIPE;
            stage(bs, j + 2);
        }
        // wait for tile j's group
        if (j < NTILES - 2)       cp_wait2();
        else if (j == NTILES - 2) cp_wait1();
        else                      cp_wait0();
        __syncwarp();

        // ---- compute tile j ----
        const float* __restrict__ xb = stg[bj];
        const float* __restrict__ wb = stg[bj] + XSTG;

        #pragma unroll
        for (int q = 0; q < 8; ++q) {           // 8 chunks of 4 i
            float4 xv[4];
            #pragma unroll
            for (int k = 0; k < 4; ++k) {
                const int row = tb + 8 * k;
                xv[k] = *(const float4*)&xb[row * 32 + ((q ^ (row & 7)) * 4)];
            }

            #pragma unroll
            for (int r = 0; r < 4; ++r) {
                const int i = q * 4 + r;
                // this lane's 4 o's = 1 LDS.128 (2 packed pairs)
                const ulonglong2 wv =
                    *(const ulonglong2*)&wb[i * OO + to * 4];

                #pragma unroll
                for (int k = 0; k < 4; ++k) {
                    const float xs = (r == 0) ? xv[k].x :
                                     (r == 1) ? xv[k].y :
                                     (r == 2) ? xv[k].z : xv[k].w;
                    const uint64_t xd = pack_dup(xs);
                    fma2(acc[k][0], xd, wv.x);
                    fma2(acc[k][1], xd, wv.y);
                }
            }
        }
        __syncwarp();   // warp done reading buffer bj before refill

        if (++bj >= PIPE) bj = 0;
    }

    // ---- epilogue ----
    const int o0 = to * 4;
    const float4 bz = *(const float4*)(bias + (size_t)c * OO + o0);

    #pragma unroll
    for (int k = 0; k < 4; ++k) {
        float v0, v1, v2, v3;
        unpack2(acc[k][0], v0, v1);
        unpack2(acc[k][1], v2, v3);

        float4 res = make_float4(v0 + bz.x, v1 + bz.y, v2 + bz.z, v3 + bz.w);

        const int b = b0 + tb + 8 * k;
        *(float4*)(out + ((size_t)b * CC + c) * OO + o0) = res;
    }
}

extern "C" void kernel_launch(void* const* d_in, const int* in_sizes, int n_in,
                              void* d_out, int out_size)
{
    (void)in_sizes; (void)n_in; (void)out_size;
    const float* x    = (const float*)d_in[0];
    const float* W    = (const float*)d_in[1];
    const float* bias = (const float*)d_in[2];
    float*       out  = (float*)d_out;

    const int smem_bytes = SMEM_FLOATS * sizeof(float);   // 72 KB
    static bool attr_done = false;
    if (!attr_done) {
        cudaFuncSetAttribute(primarycaps_kernel,
                             cudaFuncAttributeMaxDynamicSharedMemorySize,
                             smem_bytes);
        attr_done = true;
    }
    dim3 grid(BB / BH, CC / CAPS_CTA);   // (2, 1024): b-half is the FAST axis
    primarycaps_kernel<<<grid, NTH, smem_bytes>>>(x, W, bias, out);
}

// round 14
// speedup vs baseline: 1.0020x; 1.0020x over previous
#include <cuda_runtime.h>
#include <cstdint>

#define BB 64
#define CC 4096
#define IND 512
#define OO 16
#define TI 32                 // i-tile: full 128B per (b,c) row
#define NTILES (IND / TI)     // 16
#define WARPS 4
#define NTH (32 * WARPS)
#define CAPS_CTA WARPS        // 1 capsule per warp
#define BH 32                 // b-rows per CTA (page-set split, proven R9)
#define PIPE 3

#define XSTG 1024             // 32 rows x 32 words of x per warp-stage
#define WSTG 512              // 32 i-rows x 16 o of W per warp-stage
#define STG (XSTG + WSTG)     // 1536 floats = 6 KB per warp-stage
#define SMEM_FLOATS (PIPE * WARPS * STG)   // 18432 floats = 72 KB

// ---- packed f32x2 helpers ----
__device__ __forceinline__ uint64_t pack_dup(float x) {
    uint64_t r;
    asm("mov.b64 %0, {%1, %1};" : "=l"(r) : "f"(x));
    return r;
}
__device__ __forceinline__ void fma2(uint64_t& d, uint64_t a, uint64_t b) {
    asm("fma.rn.f32x2 %0, %1, %2, %0;" : "+l"(d) : "l"(a), "l"(b));
}
__device__ __forceinline__ void unpack2(uint64_t v, float& lo, float& hi) {
    asm("mov.b64 {%0, %1}, %2;" : "=f"(lo), "=f"(hi) : "l"(v));
}

// ---- cp.async 16B, L1-bypass ----
__device__ __forceinline__ void cp16(void* dst_smem, const void* src) {
    uint32_t d = (uint32_t)__cvta_generic_to_shared(dst_smem);
    asm volatile("cp.async.cg.shared.global [%0], [%1], 16;"
                 :: "r"(d), "l"(src) : "memory");
}
__device__ __forceinline__ void cp_commit() {
    asm volatile("cp.async.commit_group;" ::: "memory");
}
__device__ __forceinline__ void cp_wait2() {
    asm volatile("cp.async.wait_group 2;" ::: "memory");
}
__device__ __forceinline__ void cp_wait1() {
    asm volatile("cp.async.wait_group 1;" ::: "memory");
}
__device__ __forceinline__ void cp_wait0() {
    asm volatile("cp.async.wait_group 0;" ::: "memory");
}

extern __shared__ float sm[];

__global__ __launch_bounds__(NTH)
void primarycaps_kernel(const float* __restrict__ x,
                        const float* __restrict__ W,
                        const float* __restrict__ bias,
                        float* __restrict__ out)
{
    const int t    = threadIdx.x;
    const int wid  = t >> 5;
    const int lane = t & 31;

    // PAIR-ADJACENT SCHEDULING: blockIdx.x = b-half (fast axis) -> the two
    // CTAs sharing this CTA's W slice are linear neighbors (L2 reuse).
    const int c  = blockIdx.y * CAPS_CTA + wid;   // this warp's capsule
    const int b0 = blockIdx.x * BH;               // this CTA's b-half

    // compute map: 8 b-groups x 4 o-quarters  (mb=4, nb=4 per lane)
    const int tb = lane & 7;          // owns rows tb + 8k (k=0..3)
    const int to = lane >> 3;         // o-quarter: o = to*4 .. to*4+3

    // x staging map: one instr = 4 full 128B lines (4 rows x 8 chunks)
    const int srow = lane >> 3;       // local row 0..3 within group of 4
    const int sch  = lane & 7;        // 16B chunk 0..7 within 128B row

    // per-warp smem stage bases
    float* stg[PIPE];
    #pragma unroll
    for (int s = 0; s < PIPE; ++s)
        stg[s] = sm + (s * WARPS + wid) * STG;

    // ---- accumulators: 4 b-rows x 2 o-pairs (packed f32x2) ----
    uint64_t acc[4][2];
    #pragma unroll
    for (int k = 0; k < 4; ++k) {
        acc[k][0] = 0ULL;
        acc[k][1] = 0ULL;
    }

    // ---- stage helper: tile jt into buffer bf (this warp only) ----
    auto stage = [&](int bf, int jt) {
        float* dx = stg[bf];                   // x at +0, W at +XSTG
        // x: 8 instrs, each = 4 rows x 128B (full lines)
        #pragma unroll
        for (int g = 0; g < 8; ++g) {
            const int row = g * 4 + srow;      // 0..31
            cp16(&dx[row * 32 + ((sch ^ (row & 7)) * 4)],
                 x + ((size_t)(b0 + row) * CC + c) * IND
                   + (size_t)jt * TI + sch * 4);
        }
        // W: 4 instrs of 512B contiguous (full 2KB tile, linear layout)
        float* dw = stg[bf] + XSTG;
        #pragma unroll
        for (int m = 0; m < 4; ++m) {
            const int ofs = m * 128 + lane * 4;
            cp16(&dw[ofs],
                 W + ((size_t)c * IND + (size_t)jt * TI) * OO + ofs);
        }
        cp_commit();
    };

    // ---- prologue: 2 stages in flight ----
    stage(0, 0);
    stage(1, 1);

    int bj = 0;                        // j % PIPE
    for (int j = 0; j < NTILES; ++j) {
        // issue stage j+2 into buffer (j+2)%3 (freed last iteration)
        if (j + 2 < NTILES) {
            int bs = bj + 2; if (bs >= PIPE) bs -= PIPE;
            stage(bs, j + 2);
        }
        // wait for tile j's group
        if (j < NTILES - 2)       cp_wait2();
        else if (j == NTILES - 2) cp_wait1();
        else                      cp_wait0();
        __syncwarp();

        // ---- compute tile j ----
        const float* __restrict__ xb = stg[bj];
        const float* __restrict__ wb = stg[bj] + XSTG;

        #pragma unroll
        for (int q = 0; q < 8; ++q) {           // 8 chunks of 4 i
            float4 xv[4];
            #pragma unroll
            for (int k = 0; k < 4; ++k) {
                const int row = tb + 8 * k;
                xv[k] = *(const float4*)&xb[row * 32 + ((q ^ (row & 7)) * 4)];
            }

            #pragma unroll
            for (int r = 0; r < 4; ++r) {
                const int i = q * 4 + r;
                // this lane's 4 o's = 1 LDS.128 (2 packed pairs)
                const ulonglong2 wv =
                    *(const ulonglong2*)&wb[i * OO + to * 4];

                #pragma unroll
                for (int k = 0; k < 4; ++k) {
                    const float xs = (r == 0) ? xv[k].x :
                                     (r == 1) ? xv[k].y :
                                     (r == 2) ? xv[k].z : xv[k].w;
                    const uint64_t xd = pack_dup(xs);
                    fma2(acc[k][0], xd, wv.x);
                    fma2(acc[k][1], xd, wv.y);
                }
            }
        }
        __syncwarp();   // warp done reading buffer bj before refill

        if (++bj >= PIPE) bj = 0;
    }

    // ---- epilogue ----
    const int o0 = to * 4;
    const float4 bz = *(const float4*)(bias + (size_t)c * OO + o0);

    #pragma unroll
    for (int k = 0; k < 4; ++k) {
        float v0, v1, v2, v3;
        unpack2(acc[k][0], v0, v1);
        unpack2(acc[k][1], v2, v3);

        float4 res = make_float4(v0 + bz.x, v1 + bz.y, v2 + bz.z, v3 + bz.w);

        const int b = b0 + tb + 8 * k;
        *(float4*)(out + ((size_t)b * CC + c) * OO + o0) = res;
    }
}

extern "C" void kernel_launch(void* const* d_in, const int* in_sizes, int n_in,
                              void* d_out, int out_size)
{
    (void)in_sizes; (void)n_in; (void)out_size;
    const float* x    = (const float*)d_in[0];
    const float* W    = (const float*)d_in[1];
    const float* bias = (const float*)d_in[2];
    float*       out  = (float*)d_out;

    const int smem_bytes = SMEM_FLOATS * sizeof(float);   // 72 KB
    static bool attr_done = false;
    if (!attr_done) {
        cudaFuncSetAttribute(primarycaps_kernel,
                             cudaFuncAttributeMaxDynamicSharedMemorySize,
                             smem_bytes);
        attr_done = true;
    }
    dim3 grid(BB / BH, CC / CAPS_CTA);   // (2, 1024): b-half is the FAST axis
    primarycaps_kernel<<<grid, NTH, smem_bytes>>>(x, W, bias, out);
}